// round 1
// baseline (speedup 1.0000x reference)
#include <cuda_runtime.h>
#include <math.h>

#define NPIX   (8*256*256)      // 524288 pixels
#define NCH    32
#define NCLASS 8
#define TRI    528              // 32*33/2 packed lower-triangular
#define TPB    64               // threads per block (main kernel)
#define PPT    4                // pixels per thread
#define PPB    (TPB*PPT)        // 256 pixels per block
#define NBLK   (NPIX/PPB)       // 2048 blocks

typedef unsigned long long ull;

// Precomputed per-class constants (written by setup kernel each launch)
__device__ float2 d_Lpack[NCLASS*TRI];   // Linv packed lower-tri, splatted (v,v)
__device__ float2 d_nw[NCLASS*NCH];      // -(Linv_k @ mean_k), splatted
__device__ float  d_logc[NCLASS];        // -16*log(2pi) - logdet_k

// ---------- packed f32x2 helpers (sm_103a FFMA2 — only reachable via PTX) ----------
__device__ __forceinline__ ull ffma2(ull a, ull b, ull c) {
    ull d;
    asm("fma.rn.f32x2 %0, %1, %2, %3;" : "=l"(d) : "l"(a), "l"(b), "l"(c));
    return d;
}
__device__ __forceinline__ ull pack2(float lo, float hi) {
    ull d;
    asm("mov.b64 %0, {%1, %2};" : "=l"(d) : "f"(lo), "f"(hi));
    return d;
}
__device__ __forceinline__ float2 unpack2(ull v) {
    float lo, hi;
    asm("mov.b64 {%0, %1}, %2;" : "=f"(lo), "=f"(hi) : "l"(v));
    return make_float2(lo, hi);
}

// ---------------- setup: triangular inverse, whitened means, log-consts ----------------
// One warp per class; lane j computes column j of Linv by forward substitution,
// fully register-resident (xcol[i] = 0 for i<j falls out naturally from s=0).
__global__ void setup_kernel(const float* __restrict__ mean,
                             const float* __restrict__ scale) {
    __shared__ float sInv[NCLASS][NCH][NCH + 1];
    const int k = threadIdx.x >> 5;   // class (8 warps, 256 threads)
    const int j = threadIdx.x & 31;   // column
    const float* Lg = scale + k * NCH * NCH;

    float xcol[NCH];
    #pragma unroll
    for (int i = 0; i < NCH; i++) {
        float s = (i == j) ? 1.0f : 0.0f;
        #pragma unroll
        for (int d = 0; d < i; d++)
            s -= Lg[i * NCH + d] * xcol[d];   // lower triangle only (tril implied)
        xcol[i] = s / Lg[i * NCH + i];
    }

    #pragma unroll
    for (int i = 0; i < NCH; i++) sInv[k][i][j] = xcol[i];

    // packed splatted Linv: entry (c,d=j) at c*(c+1)/2 + j, for c >= j
    #pragma unroll
    for (int c = 0; c < NCH; c++) {
        if (j <= c)
            d_Lpack[k * TRI + c * (c + 1) / 2 + j] = make_float2(xcol[c], xcol[c]);
    }
    __syncwarp();

    // w_j = sum_{d<=j} Linv[j][d] * mean[k][d]  (store negated, splatted)
    float w = 0.0f;
    for (int d = 0; d <= j; d++)
        w += sInv[k][j][d] * mean[k * NCH + d];
    d_nw[k * NCH + j] = make_float2(-w, -w);

    if (j == 0) {
        float ld = 0.0f;
        for (int c = 0; c < NCH; c++)
            ld += logf(fabsf(Lg[c * NCH + c]));
        d_logc[k] = -16.0f * 1.8378770664093453f - ld;   // -0.5*32*log(2pi) - logdet
    }
}

// ---------------- main fused kernel ----------------
__global__ void __launch_bounds__(TPB, 4)
main_kernel(const float* __restrict__ x, float* __restrict__ out) {
    __shared__ float2 sL[NCLASS * TRI];     // 33792 B
    __shared__ float2 sNW[NCLASS * NCH];    //  2048 B
    __shared__ float  sLogc[NCLASS];        //    32 B
    __shared__ float  sG[PPB * 9];          //  9216 B  (stride 9: conflict-light)

    const int tid = threadIdx.x;
    const int pix0 = blockIdx.x * PPB + tid * PPT;

    // ---- load 4 pixels of x, packed into f32x2 pairs (px0,px1)->xA, (px2,px3)->xB
    ull xA[NCH], xB[NCH];
    {
        const float4* x4 = reinterpret_cast<const float4*>(x);
        const size_t b0 = (size_t)(pix0 + 0) * 8;
        const size_t b1 = (size_t)(pix0 + 1) * 8;
        const size_t b2 = (size_t)(pix0 + 2) * 8;
        const size_t b3 = (size_t)(pix0 + 3) * 8;
        #pragma unroll
        for (int t = 0; t < 8; t++) {
            float4 a = x4[b0 + t], b = x4[b1 + t];
            xA[4*t+0] = pack2(a.x, b.x); xA[4*t+1] = pack2(a.y, b.y);
            xA[4*t+2] = pack2(a.z, b.z); xA[4*t+3] = pack2(a.w, b.w);
        }
        #pragma unroll
        for (int t = 0; t < 8; t++) {
            float4 a = x4[b2 + t], b = x4[b3 + t];
            xB[4*t+0] = pack2(a.x, b.x); xB[4*t+1] = pack2(a.y, b.y);
            xB[4*t+2] = pack2(a.z, b.z); xB[4*t+3] = pack2(a.w, b.w);
        }
    }

    // ---- fill shared constants
    for (int i = tid; i < NCLASS * TRI; i += TPB) sL[i] = d_Lpack[i];
    for (int i = tid; i < NCLASS * NCH; i += TPB) sNW[i] = d_nw[i];
    if (tid < NCLASS) sLogc[tid] = d_logc[tid];
    __syncthreads();

    // ---- per-class triangular whitening: z = Linv x - w ; maha = sum z^2
    #pragma unroll 1
    for (int k = 0; k < NCLASS; k++) {
        const ull* Lk  = reinterpret_cast<const ull*>(sL  + k * TRI);
        const ull* nwk = reinterpret_cast<const ull*>(sNW + k * NCH);
        ull mA = 0ULL, mB = 0ULL;   // (+0.0f, +0.0f)
        #pragma unroll
        for (int c = 0; c < NCH; c++) {
            ull zA = nwk[c];
            ull zB = zA;
            #pragma unroll
            for (int d = 0; d <= c; d++) {
                ull lv = Lk[c * (c + 1) / 2 + d];   // LDS.64 broadcast, splatted
                zA = ffma2(xA[d], lv, zA);
                zB = ffma2(xB[d], lv, zB);
            }
            mA = ffma2(zA, zA, mA);
            mB = ffma2(zB, zB, mB);
        }
        float2 a = unpack2(mA), b = unpack2(mB);
        float lc = sLogc[k];
        int base = (tid * PPT) * 9 + k;
        sG[base     ] = fmaf(-0.5f, a.x, lc);
        sG[base +  9] = fmaf(-0.5f, a.y, lc);
        sG[base + 18] = fmaf(-0.5f, b.x, lc);
        sG[base + 27] = fmaf(-0.5f, b.y, lc);
    }

    // ---- epilogue: log-probs -> l2-normalized (with 1e-12 clamp) gauss weights
    #pragma unroll
    for (int q = 0; q < PPT; q++) {
        const int p = tid * PPT + q;
        float lp[NCLASS];
        #pragma unroll
        for (int k = 0; k < NCLASS; k++) lp[k] = sG[p * 9 + k];
        float m = lp[0];
        #pragma unroll
        for (int k = 1; k < NCLASS; k++) m = fmaxf(m, lp[k]);
        float pr[NCLASS];
        float s = 0.0f;
        #pragma unroll
        for (int k = 0; k < NCLASS; k++) {
            pr[k] = __expf(lp[k] - m);
            s = fmaf(pr[k], pr[k], s);     // s >= 1 always (max term is 1)
        }
        float em = __expf(m);
        float t = em * em * s;             // true sum(prob^2); underflow -> clamp path
        float sc = (t >= 1e-12f) ? rsqrtf(s) : (em * 1.0e6f);
        #pragma unroll
        for (int k = 0; k < NCLASS; k++) sG[p * 9 + k] = pr[k] * sc;
    }
    __syncthreads();

    // ---- store phase: one warp per pixel, fully coalesced 512B STG.128 bursts
    const int lane = tid & 31;
    const int wrp  = tid >> 5;
    const float4* x4 = reinterpret_cast<const float4*>(x);
    float4* o4 = reinterpret_cast<float4*>(out);
    for (int p = wrp; p < PPB; p += TPB / 32) {
        const size_t gp = (size_t)blockIdx.x * PPB + p;
        float4 xv = __ldg(&x4[gp * 8 + (lane & 7)]);        // one 128B line, L1-hot
        float g0 = sG[p * 9 + (lane >> 3)];                 // classes 0..3
        float g1 = sG[p * 9 + 4 + (lane >> 3)];             // classes 4..7
        float4 r0, r1;
        r0.x = xv.x * g0; r0.y = xv.y * g0; r0.z = xv.z * g0; r0.w = xv.w * g0;
        r1.x = xv.x * g1; r1.y = xv.y * g1; r1.z = xv.z * g1; r1.w = xv.w * g1;
        __stcs(&o4[gp * 64 + lane],      r0);               // streaming: don't thrash L2
        __stcs(&o4[gp * 64 + 32 + lane], r1);
    }
}

extern "C" void kernel_launch(void* const* d_in, const int* in_sizes, int n_in,
                              void* d_out, int out_size) {
    const float* x     = (const float*)d_in[0];   // [8,256,256,32]
    const float* mean  = (const float*)d_in[1];   // [8,32]
    const float* scale = (const float*)d_in[2];   // [8,32,32]
    float* out = (float*)d_out;                   // [8,256,256,256]

    setup_kernel<<<1, 256>>>(mean, scale);
    main_kernel<<<NBLK, TPB>>>(x, out);
}